// round 11
// baseline (speedup 1.0000x reference)
#include <cuda_runtime.h>

#define NN      25
#define GPBK    16             // graphs per block = warps per block
#define THREADS 512
#define OFFW    7              // s_off per-node row stride (6 used, odd -> conflict-free)
#define LW      12             // fused row: [R0..8 | x,y,z]; 48B, 16B-aligned

// combine: W[i] = (Rp * Li, Rp * xyz_i + pos_p), all rows are float4-aligned LW=12 rows
__device__ __forceinline__ void tree_combine(int i, const float* __restrict__ Lg,
                                             float* __restrict__ Wg)
{
    const int par = (i - 1) >> 1;
    const float4* wp = (const float4*)(Wg + par * LW);
    const float4 WA = wp[0], WB = wp[1], WC = wp[2];   // Rp | pos_p in WC.yzw
    const float4* lp = (const float4*)(Lg + i * LW);
    const float4 LA = lp[0], LB = lp[1], LC = lp[2];   // Li | xyz_i in LC.yzw

    float4 OA, OB, OC;
    OC.y = WA.x*LC.y + WA.y*LC.z + WA.z*LC.w + WC.y;
    OC.z = WA.w*LC.y + WB.x*LC.z + WB.y*LC.w + WC.z;
    OC.w = WB.z*LC.y + WB.w*LC.z + WC.x*LC.w + WC.w;
    OA.x = WA.x*LA.x + WA.y*LA.w + WA.z*LB.z;
    OA.y = WA.x*LA.y + WA.y*LB.x + WA.z*LB.w;
    OA.z = WA.x*LA.z + WA.y*LB.y + WA.z*LC.x;
    OA.w = WA.w*LA.x + WB.x*LA.w + WB.y*LB.z;
    OB.x = WA.w*LA.y + WB.x*LB.x + WB.y*LB.w;
    OB.y = WA.w*LA.z + WB.x*LB.y + WB.y*LC.x;
    OB.z = WB.z*LA.x + WB.w*LA.w + WC.x*LB.z;
    OB.w = WB.z*LA.y + WB.w*LB.x + WC.x*LB.w;
    OC.x = WB.z*LA.z + WB.w*LB.y + WC.x*LC.x;

    float4* wo = (float4*)(Wg + i * LW);
    wo[0] = OA; wo[1] = OB; wo[2] = OC;
}

__global__ void __launch_bounds__(THREADS, 3)
fk_kernel(const float* __restrict__ x,
          const float* __restrict__ off,
          const float* __restrict__ axis,
          float* __restrict__ out_pos,
          float* __restrict__ out_rot,
          float* __restrict__ out_gpos,
          int G)
{
    __shared__ float s_off[GPBK * NN * OFFW];                 // 2800
    __shared__ __align__(16) float s_L[GPBK * NN * LW];       // 4800
    __shared__ __align__(16) float s_W[GPBK * NN * LW];       // 4800
    __shared__ float4 s_ax[NN];

    const int t = threadIdx.x;
    if (t < NN) {
        const float a0 = axis[t*3+0], a1 = axis[t*3+1], a2 = axis[t*3+2];
        s_ax[t] = make_float4(a0, a1, a2, sqrtf(a0*a0 + a1*a1 + a2*a2));
    }
    __syncthreads();

    const int lane = t & 31, w = t >> 5;
    const int g = blockIdx.x * GPBK + w;        // one graph per warp
    if (g >= G) return;                          // warp-uniform

    float* s_off_g = s_off + w * (NN * OFFW);
    float* Lg      = s_L   + w * (NN * LW);
    float* Wg      = s_W   + w * (NN * LW);

    // ---- stage this graph's 150 offset floats (coalesced LDG, conflict-lite STS) ----
    {
        const float* src = off + (size_t)g * 150;
        #pragma unroll
        for (int it = 0; it < 5; it++) {
            const int idx = lane + 32 * it;
            if (idx < 150) {
                const int row = idx / 6;
                s_off_g[row * OFFW + (idx - row * 6)] = src[idx];
            }
        }
    }
    __syncwarp();

    // ---- phase 1: lanes 0..24 build fused local rows [L | xyz]; lane 0 also seeds W[0] ----
    if (lane < NN) {
        const float* o = s_off_g + lane * OFFW;
        const float4 ax = s_ax[lane];
        const float th = x[(size_t)g * NN + lane] * ax.w;
        const float ox = o[0], oy = o[1], oz = o[2];

        float sx,cx,sy,cy,sz,cz,st,ct;
        __sincosf(o[3], &sx, &cx);
        __sincosf(o[4], &sy, &cy);
        __sincosf(o[5], &sz, &cz);
        __sincosf(th,  &st, &ct);

        const float e00=cz*cy,            e10=sz*cy,            e20=-sy;
        const float e01=cz*sy*sx - sz*cx, e11=sz*sy*sx + cz*cx, e21=cy*sx;
        const float e02=cz*sy*cx + sz*sx, e12=sz*sy*cx - cz*sx, e22=cy*cx;

        const float v=1.f-ct, n1=ax.x, n2=ax.y, n3=ax.z;
        const float n12v=n1*n2*v, n13v=n1*n3*v, n23v=n2*n3*v;
        const float r00=ct+n1*n1*v, r01=n12v-n3*st, r02=n13v+n2*st;
        const float r10=n12v+n3*st, r11=ct+n2*n2*v, r12=n23v-n1*st;
        const float r20=n13v-n2*st, r21=n23v+n1*st, r22=ct+n3*n3*v;

        float4 A, B, C;
        A.x=e00*r00+e01*r10+e02*r20; A.y=e00*r01+e01*r11+e02*r21; A.z=e00*r02+e01*r12+e02*r22;
        A.w=e10*r00+e11*r10+e12*r20; B.x=e10*r01+e11*r11+e12*r21; B.y=e10*r02+e11*r12+e12*r22;
        B.z=e20*r00+e21*r10+e22*r20; B.w=e20*r01+e21*r11+e22*r21; C.x=e20*r02+e21*r12+e22*r22;
        C.y=ox; C.z=oy; C.w=oz;

        float4* row = (float4*)(Lg + lane * LW);
        row[0] = A; row[1] = B; row[2] = C;

        if (lane == 0) {                      // W[0] = [L0 | pos=0]
            float4 C0 = C; C0.y = 0.f; C0.z = 0.f; C0.w = 0.f;
            float4* w0 = (float4*)Wg;
            w0[0] = A; w0[1] = B; w0[2] = C0;
        }
    }
    __syncwarp();

    // ---- level-synchronous tree pass: 24 combines total, 1-step dependency ----
    if (lane < 2)  tree_combine(1 + lane, Lg, Wg);     // level 1: nodes 1..2
    __syncwarp();
    if (lane < 4)  tree_combine(3 + lane, Lg, Wg);     // level 2: nodes 3..6
    __syncwarp();
    if (lane < 8)  tree_combine(7 + lane, Lg, Wg);     // level 3: nodes 7..14
    __syncwarp();
    if (lane < 10) tree_combine(15 + lane, Lg, Wg);    // level 4: nodes 15..24
    __syncwarp();

    // ---- flush directly from s_W (coalesced STG; broadcast root xyz for gpos) ----
    const float rx = Lg[9], ry = Lg[10], rz = Lg[11];   // node-0 xyz (broadcast LDS)
    {
        float* dp = out_pos  + (size_t)g * 75;
        float* dg = out_gpos + (size_t)g * 75;
        #pragma unroll
        for (int it = 0; it < 3; it++) {
            const int idx = lane + 32 * it;
            if (idx < 75) {
                const int row = idx / 3;
                const int j   = idx - row * 3;
                const float v = Wg[row * LW + 9 + j];
                dp[idx] = v;
                dg[idx] = v + (j == 0 ? rx : (j == 1 ? ry : rz));
            }
        }
        float* dr = out_rot + (size_t)g * 225;
        #pragma unroll
        for (int it = 0; it < 8; it++) {
            const int idx = lane + 32 * it;
            if (idx < 225) {
                const int row = idx / 9;
                dr[idx] = Wg[row * LW + (idx - row * 9)];
            }
        }
    }
}

extern "C" void kernel_launch(void* const* d_in, const int* in_sizes, int n_in,
                              void* d_out, int out_size)
{
    const float* x = (const float*)d_in[0];
    const int gn = in_sizes[0];          // G * 25
    const int G  = gn / NN;

    const float* off = nullptr;
    const float* axis = nullptr;
    for (int i = 1; i < n_in; i++) {
        if (in_sizes[i] == 6 * gn) off = (const float*)d_in[i];
        else if (in_sizes[i] == 3 * gn && axis == nullptr) axis = (const float*)d_in[i];
    }

    float* out = (float*)d_out;
    float* out_pos  = out;                    // G*N*3
    float* out_rot  = out + (size_t)gn * 3;   // G*N*9
    float* out_gpos = out + (size_t)gn * 12;  // G*N*3
    (void)out_size;

    const int blocks = (G + GPBK - 1) / GPBK;
    fk_kernel<<<blocks, THREADS>>>(x, off, axis, out_pos, out_rot, out_gpos, G);
}

// round 12
// speedup vs baseline: 1.0768x; 1.0768x over previous
#include <cuda_runtime.h>

#define NN     25
#define GPBK   16              // graphs per block
#define THREADS 448            // 400 compute threads (16*25), warp-aligned depth classes
#define LW     12              // s_L row: L[9] + xyz[3]; 48B, 16B-aligned

// packed root-paths, low byte = root child ... high = self (unused bytes = 0)
__constant__ unsigned int c_pp[NN] = {
    0u,                                   // 0 (root, unused)
    1u,                                   // 1
    2u,                                   // 2
    (1u)|(3u<<8),                         // 3
    (1u)|(4u<<8),                         // 4
    (2u)|(5u<<8),                         // 5
    (2u)|(6u<<8),                         // 6
    (1u)|(3u<<8)|(7u<<16),                // 7
    (1u)|(3u<<8)|(8u<<16),                // 8
    (1u)|(4u<<8)|(9u<<16),                // 9
    (1u)|(4u<<8)|(10u<<16),               // 10
    (2u)|(5u<<8)|(11u<<16),               // 11
    (2u)|(5u<<8)|(12u<<16),               // 12
    (2u)|(6u<<8)|(13u<<16),               // 13
    (2u)|(6u<<8)|(14u<<16),               // 14
    (1u)|(3u<<8)|(7u<<16)|(15u<<24),      // 15
    (1u)|(3u<<8)|(7u<<16)|(16u<<24),      // 16
    (1u)|(3u<<8)|(8u<<16)|(17u<<24),      // 17
    (1u)|(3u<<8)|(8u<<16)|(18u<<24),      // 18
    (1u)|(4u<<8)|(9u<<16)|(19u<<24),      // 19
    (1u)|(4u<<8)|(9u<<16)|(20u<<24),      // 20
    (1u)|(4u<<8)|(10u<<16)|(21u<<24),     // 21
    (1u)|(4u<<8)|(10u<<16)|(22u<<24),     // 22
    (2u)|(5u<<8)|(11u<<16)|(23u<<24),     // 23
    (2u)|(5u<<8)|(11u<<16)|(24u<<24)      // 24
};

// exact-depth prefix-product walk; reads fused rows [L0..8 | ox,oy,oz] via LDS.128
template<int STEPS>
__device__ __forceinline__ void walk_store(
    const float* __restrict__ Lg, unsigned int pk,
    float* __restrict__ sp, float* __restrict__ sg, float* __restrict__ sr)
{
    const float4* rp = (const float4*)Lg;          // root row
    const float4 A = rp[0], B = rp[1], C = rp[2];
    float R0=A.x,R1=A.y,R2=A.z,R3=A.w,R4=B.x,R5=B.y,R6=B.z,R7=B.w,R8=C.x;
    const float rx=C.y, ry=C.z, rz=C.w;
    float p0=0.f, p1=0.f, p2=0.f;

    #pragma unroll
    for (int k = 0; k < STEPS; k++) {
        const int a = pk & 255u; pk >>= 8;
        const float4* ap = (const float4*)(Lg + a * LW);
        const float4 LA = ap[0], LB = ap[1], LC = ap[2];
        p0 += R0*LC.y + R1*LC.z + R2*LC.w;
        p1 += R3*LC.y + R4*LC.z + R5*LC.w;
        p2 += R6*LC.y + R7*LC.z + R8*LC.w;
        const float n0 = R0*LA.x + R1*LA.w + R2*LB.z;
        const float n1 = R0*LA.y + R1*LB.x + R2*LB.w;
        const float n2 = R0*LA.z + R1*LB.y + R2*LC.x;
        const float n3 = R3*LA.x + R4*LA.w + R5*LB.z;
        const float n4 = R3*LA.y + R4*LB.x + R5*LB.w;
        const float n5 = R3*LA.z + R4*LB.y + R5*LC.x;
        const float n6 = R6*LA.x + R7*LA.w + R8*LB.z;
        const float n7 = R6*LA.y + R7*LB.x + R8*LB.w;
        const float n8 = R6*LA.z + R7*LB.y + R8*LC.x;
        R0=n0; R1=n1; R2=n2; R3=n3; R4=n4; R5=n5; R6=n6; R7=n7; R8=n8;
    }

    sp[0]=p0; sp[1]=p1; sp[2]=p2;
    sg[0]=p0+rx; sg[1]=p1+ry; sg[2]=p2+rz;
    sr[0]=R0; sr[1]=R1; sr[2]=R2; sr[3]=R3; sr[4]=R4;
    sr[5]=R5; sr[6]=R6; sr[7]=R7; sr[8]=R8;
}

__global__ void __launch_bounds__(THREADS, 4)
fk_kernel(const float* __restrict__ x,
          const float* __restrict__ off,
          const float* __restrict__ axis,
          float* __restrict__ out_pos,
          float* __restrict__ out_rot,
          float* __restrict__ out_gpos,
          int G)
{
    __shared__ __align__(16) float s_off[GPBK * NN * 6];   // 2400
    __shared__ __align__(16) float s_L  [GPBK * NN * LW];  // 4800
    __shared__ __align__(16) float s_pos[GPBK * NN * 3];   // 1200 (output layout)
    __shared__ __align__(16) float s_gps[GPBK * NN * 3];   // 1200
    __shared__ __align__(16) float s_rot[GPBK * NN * 9];   // 3600
    __shared__ float4 s_ax[NN];
    __shared__ unsigned int s_pp[NN];

    const int t  = threadIdx.x;
    const int g0 = blockIdx.x * GPBK;
    const int ng = min(GPBK, G - g0);
    const int NT = ng * NN;

    // ---- stage axis/paths/offsets ----
    if (t < NN) {
        const float a0 = axis[t*3+0], a1 = axis[t*3+1], a2 = axis[t*3+2];
        s_ax[t] = make_float4(a0, a1, a2, sqrtf(a0*a0 + a1*a1 + a2*a2));
        s_pp[t] = c_pp[t];
    }
    if (ng == GPBK) {
        const float4* srcv = (const float4*)(off + (size_t)g0 * 150);
        float4* dv = (float4*)s_off;
        // 600 float4s over 448 threads: iter 1 full, iter 2 predicated
        dv[t] = srcv[t];
        if (t < 600 - THREADS) dv[t + THREADS] = srcv[t + THREADS];
    } else {
        const float* src = off + (size_t)g0 * 150;
        for (int i = t; i < NT * 6; i += THREADS) s_off[i] = src[i];
    }
    __syncthreads();

    // ---- phase 1: per-node local matrix -> fused row [L0..8, ox,oy,oz] ----
    if (t < NT) {
        const int i = t - 25 * (t / 25);
        const float* o = s_off + t * 6;
        const float4 ax = s_ax[i];
        const float th = x[(size_t)g0 * NN + t] * ax.w;     // coalesced LDG
        const float ox = o[0], oy = o[1], oz = o[2];

        float sx,cx,sy,cy,sz,cz,st,ct;
        __sincosf(o[3], &sx, &cx);
        __sincosf(o[4], &sy, &cy);
        __sincosf(o[5], &sz, &cz);
        __sincosf(th,  &st, &ct);

        const float e00=cz*cy,            e10=sz*cy,            e20=-sy;
        const float e01=cz*sy*sx - sz*cx, e11=sz*sy*sx + cz*cx, e21=cy*sx;
        const float e02=cz*sy*cx + sz*sx, e12=sz*sy*cx - cz*sx, e22=cy*cx;

        const float v=1.f-ct, n1=ax.x, n2=ax.y, n3=ax.z;
        const float n12v=n1*n2*v, n13v=n1*n3*v, n23v=n2*n3*v;
        const float r00=ct+n1*n1*v, r01=n12v-n3*st, r02=n13v+n2*st;
        const float r10=n12v+n3*st, r11=ct+n2*n2*v, r12=n23v-n1*st;
        const float r20=n13v-n2*st, r21=n23v+n1*st, r22=ct+n3*n3*v;

        float4 A, B, C;
        A.x=e00*r00+e01*r10+e02*r20; A.y=e00*r01+e01*r11+e02*r21; A.z=e00*r02+e01*r12+e02*r22;
        A.w=e10*r00+e11*r10+e12*r20; B.x=e10*r01+e11*r11+e12*r21; B.y=e10*r02+e11*r12+e12*r22;
        B.z=e20*r00+e21*r10+e22*r20; B.w=e20*r01+e21*r11+e22*r21; C.x=e20*r02+e21*r12+e22*r22;
        C.y=ox; C.z=oy; C.w=oz;

        float4* row = (float4*)(s_L + t * LW);
        row[0] = A; row[1] = B; row[2] = C;
    }
    __syncthreads();

    // ---- phase 2: depth-classed walk; classes are whole warps, loops exactly unrolled ----
    if (t < 160) {                                        // depth-4 leaves 15..24 (5 warps)
        const int g = t / 10, node = 15 + (t - g * 10);
        if (g < ng) {
            const int r = g * NN + node;
            walk_store<4>(s_L + g*NN*LW, s_pp[node], s_pos + r*3, s_gps + r*3, s_rot + r*9);
        }
    } else if (t < 288) {                                 // depth-3 nodes 7..14 (4 warps)
        const int i = t - 160, g = i >> 3, node = 7 + (i & 7);
        if (g < ng) {
            const int r = g * NN + node;
            walk_store<3>(s_L + g*NN*LW, s_pp[node], s_pos + r*3, s_gps + r*3, s_rot + r*9);
        }
    } else if (t < 352) {                                 // depth-2 nodes 3..6 (2 warps)
        const int i = t - 288, g = i >> 2, node = 3 + (i & 3);
        if (g < ng) {
            const int r = g * NN + node;
            walk_store<2>(s_L + g*NN*LW, s_pp[node], s_pos + r*3, s_gps + r*3, s_rot + r*9);
        }
    } else if (t < 384) {                                 // depth-1 nodes 1..2 (1 warp)
        const int i = t - 352, g = i >> 1, node = 1 + (i & 1);
        if (g < ng) {
            const int r = g * NN + node;
            walk_store<1>(s_L + g*NN*LW, s_pp[node], s_pos + r*3, s_gps + r*3, s_rot + r*9);
        }
    } else if (t < 400) {                                 // root (half warp)
        const int g = t - 384;
        if (g < ng) {
            const int r = g * NN;
            walk_store<0>(s_L + g*NN*LW, 0u, s_pos + r*3, s_gps + r*3, s_rot + r*9);
        }
    }
    __syncthreads();

    // ---- flush: pure float4 copies, fixed trip counts ----
    if (ng == GPBK) {
        const float4* sp4 = (const float4*)s_pos;
        const float4* sg4 = (const float4*)s_gps;
        const float4* sr4 = (const float4*)s_rot;
        float4* dp4 = (float4*)(out_pos  + (size_t)g0 * 75);
        float4* dg4 = (float4*)(out_gpos + (size_t)g0 * 75);
        float4* dr4 = (float4*)(out_rot  + (size_t)g0 * 225);
        if (t < 300) { dp4[t] = sp4[t]; dg4[t] = sg4[t]; }    // 300 float4 each
        dr4[t] = sr4[t];                                       // 900 float4
        dr4[t + THREADS] = sr4[t + THREADS];
        if (t < 900 - 2*THREADS) dr4[t + 2*THREADS] = sr4[t + 2*THREADS];
    } else {
        float* dp = out_pos  + (size_t)g0 * 75;
        float* dg = out_gpos + (size_t)g0 * 75;
        float* dr = out_rot  + (size_t)g0 * 225;
        for (int idx = t; idx < NT * 3; idx += THREADS) { dp[idx] = s_pos[idx]; dg[idx] = s_gps[idx]; }
        for (int idx = t; idx < NT * 9; idx += THREADS) dr[idx] = s_rot[idx];
    }
}

extern "C" void kernel_launch(void* const* d_in, const int* in_sizes, int n_in,
                              void* d_out, int out_size)
{
    const float* x = (const float*)d_in[0];
    const int gn = in_sizes[0];          // G * 25
    const int G  = gn / NN;

    const float* off = nullptr;
    const float* axis = nullptr;
    for (int i = 1; i < n_in; i++) {
        if (in_sizes[i] == 6 * gn) off = (const float*)d_in[i];
        else if (in_sizes[i] == 3 * gn && axis == nullptr) axis = (const float*)d_in[i];
    }

    float* out = (float*)d_out;
    float* out_pos  = out;                    // G*N*3
    float* out_rot  = out + (size_t)gn * 3;   // G*N*9
    float* out_gpos = out + (size_t)gn * 12;  // G*N*3
    (void)out_size;

    const int blocks = (G + GPBK - 1) / GPBK;
    fk_kernel<<<blocks, THREADS>>>(x, off, axis, out_pos, out_rot, out_gpos, G);
}

// round 13
// speedup vs baseline: 1.1374x; 1.0563x over previous
#include <cuda_runtime.h>

#define NN     25
#define GPBK   16              // graphs per block
#define THREADS 448
#define LW     12              // fused row: [R0..8 | x,y,z]; 48B, 16B-aligned
#define GROW   (NN * LW)       // 300 floats per graph in s_L

struct A9 { float R[9]; float p[3]; };

__device__ __forceinline__ A9 load_row(const float* __restrict__ row) {
    const float4* rp = (const float4*)row;
    const float4 a = rp[0], b = rp[1], c = rp[2];
    A9 o;
    o.R[0]=a.x; o.R[1]=a.y; o.R[2]=a.z; o.R[3]=a.w; o.R[4]=b.x; o.R[5]=b.y;
    o.R[6]=b.z; o.R[7]=b.w; o.R[8]=c.x; o.p[0]=c.y; o.p[1]=c.z; o.p[2]=c.w;
    return o;
}

// W = W ∘ (L, xyz):  p += R*xyz ; R = R*L
__device__ __forceinline__ void step(A9& W, const float* __restrict__ Lrow) {
    const float4* lp = (const float4*)Lrow;
    const float4 LA = lp[0], LB = lp[1], LC = lp[2];
    W.p[0] += W.R[0]*LC.y + W.R[1]*LC.z + W.R[2]*LC.w;
    W.p[1] += W.R[3]*LC.y + W.R[4]*LC.z + W.R[5]*LC.w;
    W.p[2] += W.R[6]*LC.y + W.R[7]*LC.z + W.R[8]*LC.w;
    const float n0 = W.R[0]*LA.x + W.R[1]*LA.w + W.R[2]*LB.z;
    const float n1 = W.R[0]*LA.y + W.R[1]*LB.x + W.R[2]*LB.w;
    const float n2 = W.R[0]*LA.z + W.R[1]*LB.y + W.R[2]*LC.x;
    const float n3 = W.R[3]*LA.x + W.R[4]*LA.w + W.R[5]*LB.z;
    const float n4 = W.R[3]*LA.y + W.R[4]*LB.x + W.R[5]*LB.w;
    const float n5 = W.R[3]*LA.z + W.R[4]*LB.y + W.R[5]*LC.x;
    const float n6 = W.R[6]*LA.x + W.R[7]*LA.w + W.R[8]*LB.z;
    const float n7 = W.R[6]*LA.y + W.R[7]*LB.x + W.R[8]*LB.w;
    const float n8 = W.R[6]*LA.z + W.R[7]*LB.y + W.R[8]*LC.x;
    W.R[0]=n0; W.R[1]=n1; W.R[2]=n2; W.R[3]=n3; W.R[4]=n4;
    W.R[5]=n5; W.R[6]=n6; W.R[7]=n7; W.R[8]=n8;
}

__device__ __forceinline__ void store_w(float* __restrict__ row, const A9& W) {
    float4* rp = (float4*)row;
    rp[0] = make_float4(W.R[0], W.R[1], W.R[2], W.R[3]);
    rp[1] = make_float4(W.R[4], W.R[5], W.R[6], W.R[7]);
    rp[2] = make_float4(W.R[8], W.p[0], W.p[1], W.p[2]);
}

__device__ __forceinline__ void stage_out(int r, const A9& W,
    float rx, float ry, float rz,
    float* __restrict__ s_pos, float* __restrict__ s_gps, float* __restrict__ s_rot)
{
    float* sp = s_pos + r*3;
    float* sg = s_gps + r*3;
    float* sr = s_rot + r*9;
    sp[0]=W.p[0]; sp[1]=W.p[1]; sp[2]=W.p[2];
    sg[0]=W.p[0]+rx; sg[1]=W.p[1]+ry; sg[2]=W.p[2]+rz;
    #pragma unroll
    for (int k=0;k<9;k++) sr[k]=W.R[k];
}

__global__ void __launch_bounds__(THREADS, 4)
fk_kernel(const float* __restrict__ x,
          const float* __restrict__ off,
          const float* __restrict__ axis,
          float* __restrict__ out_pos,
          float* __restrict__ out_rot,
          float* __restrict__ out_gpos,
          int G)
{
    __shared__ __align__(16) float s_off[GPBK * NN * 6];   // 2400; reused as s_W in phase 2
    __shared__ __align__(16) float s_L  [GPBK * GROW];     // 4800
    __shared__ __align__(16) float s_pos[GPBK * NN * 3];   // 1200 (output layout)
    __shared__ __align__(16) float s_gps[GPBK * NN * 3];   // 1200
    __shared__ __align__(16) float s_rot[GPBK * NN * 9];   // 3600
    __shared__ float4 s_ax[NN];
    float* s_W = s_off;   // W rows for nodes 1..6: (g*6 + node-1)*LW; 1152 <= 2400

    const int t  = threadIdx.x;
    const int g0 = blockIdx.x * GPBK;
    const int ng = min(GPBK, G - g0);
    const int NT = ng * NN;

    // ---- stage axis + offsets ----
    if (t < NN) {
        const float a0 = axis[t*3+0], a1 = axis[t*3+1], a2 = axis[t*3+2];
        s_ax[t] = make_float4(a0, a1, a2, sqrtf(a0*a0 + a1*a1 + a2*a2));
    }
    if (ng == GPBK) {
        const float4* srcv = (const float4*)(off + (size_t)g0 * 150);
        float4* dv = (float4*)s_off;
        dv[t] = srcv[t];
        if (t < 600 - THREADS) dv[t + THREADS] = srcv[t + THREADS];
    } else {
        const float* src = off + (size_t)g0 * 150;
        for (int i = t; i < NT * 6; i += THREADS) s_off[i] = src[i];
    }
    __syncthreads();

    // ---- phase 1: per-node local matrix -> fused row [L0..8, ox,oy,oz] ----
    if (t < NT) {
        const int i = t - 25 * (t / 25);
        const float* o = s_off + t * 6;
        const float4 ax = s_ax[i];
        const float th = x[(size_t)g0 * NN + t] * ax.w;     // coalesced LDG
        const float ox = o[0], oy = o[1], oz = o[2];

        float sx,cx,sy,cy,sz,cz,st,ct;
        __sincosf(o[3], &sx, &cx);
        __sincosf(o[4], &sy, &cy);
        __sincosf(o[5], &sz, &cz);
        __sincosf(th,  &st, &ct);

        const float e00=cz*cy,            e10=sz*cy,            e20=-sy;
        const float e01=cz*sy*sx - sz*cx, e11=sz*sy*sx + cz*cx, e21=cy*sx;
        const float e02=cz*sy*cx + sz*sx, e12=sz*sy*cx - cz*sx, e22=cy*cx;

        const float v=1.f-ct, n1=ax.x, n2=ax.y, n3=ax.z;
        const float n12v=n1*n2*v, n13v=n1*n3*v, n23v=n2*n3*v;
        const float r00=ct+n1*n1*v, r01=n12v-n3*st, r02=n13v+n2*st;
        const float r10=n12v+n3*st, r11=ct+n2*n2*v, r12=n23v-n1*st;
        const float r20=n13v-n2*st, r21=n23v+n1*st, r22=ct+n3*n3*v;

        float4 A, B, C;
        A.x=e00*r00+e01*r10+e02*r20; A.y=e00*r01+e01*r11+e02*r21; A.z=e00*r02+e01*r12+e02*r22;
        A.w=e10*r00+e11*r10+e12*r20; B.x=e10*r01+e11*r11+e12*r21; B.y=e10*r02+e11*r12+e12*r22;
        B.z=e20*r00+e21*r10+e22*r20; B.w=e20*r01+e21*r11+e22*r21; C.x=e20*r02+e21*r12+e22*r22;
        C.y=ox; C.z=oy; C.w=oz;

        float4* row = (float4*)(s_L + t * LW);
        row[0] = A; row[1] = B; row[2] = C;
    }
    __syncthreads();   // also: s_off no longer read; safe to write s_W below

    // ---- phase 2a level 1: nodes 1,2 (1 warp, packed across graphs) ----
    if (t < 2 * GPBK) {
        const int g = t >> 1, node = 1 + (t & 1);
        if (g < ng) {
            const float* Lg = s_L + g * GROW;
            A9 W = load_row(Lg);                      // (L0 | xyz0)
            const float rx = W.p[0], ry = W.p[1], rz = W.p[2];
            W.p[0] = 0.f; W.p[1] = 0.f; W.p[2] = 0.f; // W0 = (L0, 0)
            step(W, Lg + node * LW);
            store_w(s_W + (g*6 + node-1) * LW, W);
            stage_out(g*NN + node, W, rx, ry, rz, s_pos, s_gps, s_rot);
        }
    }
    __syncthreads();

    // ---- phase 2a level 2: nodes 3..6 (2 warps) ----
    if (t < 4 * GPBK) {
        const int g = t >> 2, j = t & 3, node = 3 + j, par = 1 + (j >> 1);
        if (g < ng) {
            const float* Lg = s_L + g * GROW;
            A9 W = load_row(s_W + (g*6 + par-1) * LW);
            step(W, Lg + node * LW);
            store_w(s_W + (g*6 + node-1) * LW, W);
            const float rx = Lg[9], ry = Lg[10], rz = Lg[11];
            stage_out(g*NN + node, W, rx, ry, rz, s_pos, s_gps, s_rot);
        }
    }
    __syncthreads();

    // ---- phase 2b: short walks from level-2 ancestors + root staging ----
    if (t < 160) {                       // depth-4 leaves 15..24: 2 steps (5 warps)
        const int g = t / 10, j = t - g * 10, node = 15 + j;
        const int anc3 = 7 + (j >> 1), anc2 = 3 + (j >> 2);
        if (g < ng) {
            const float* Lg = s_L + g * GROW;
            A9 W = load_row(s_W + (g*6 + anc2-1) * LW);
            step(W, Lg + anc3 * LW);
            step(W, Lg + node * LW);
            stage_out(g*NN + node, W, Lg[9], Lg[10], Lg[11], s_pos, s_gps, s_rot);
        }
    } else if (t < 288) {                // depth-3 nodes 7..14: 1 step (4 warps)
        const int i = t - 160, g = i >> 3, j = i & 7, node = 7 + j, par = 3 + (j >> 1);
        if (g < ng) {
            const float* Lg = s_L + g * GROW;
            A9 W = load_row(s_W + (g*6 + par-1) * LW);
            step(W, Lg + node * LW);
            stage_out(g*NN + node, W, Lg[9], Lg[10], Lg[11], s_pos, s_gps, s_rot);
        }
    } else if (t < 288 + GPBK) {         // root outputs (half warp)
        const int g = t - 288;
        if (g < ng) {
            const float* Lg = s_L + g * GROW;
            A9 W = load_row(Lg);
            const float rx = W.p[0], ry = W.p[1], rz = W.p[2];
            W.p[0] = 0.f; W.p[1] = 0.f; W.p[2] = 0.f;
            stage_out(g*NN, W, rx, ry, rz, s_pos, s_gps, s_rot);
        }
    }
    __syncthreads();

    // ---- flush: pure float4 copies, fixed trip counts ----
    if (ng == GPBK) {
        const float4* sp4 = (const float4*)s_pos;
        const float4* sg4 = (const float4*)s_gps;
        const float4* sr4 = (const float4*)s_rot;
        float4* dp4 = (float4*)(out_pos  + (size_t)g0 * 75);
        float4* dg4 = (float4*)(out_gpos + (size_t)g0 * 75);
        float4* dr4 = (float4*)(out_rot  + (size_t)g0 * 225);
        if (t < 300) { dp4[t] = sp4[t]; dg4[t] = sg4[t]; }    // 300 float4 each
        dr4[t] = sr4[t];                                       // 900 float4
        dr4[t + THREADS] = sr4[t + THREADS];
        if (t < 900 - 2*THREADS) dr4[t + 2*THREADS] = sr4[t + 2*THREADS];
    } else {
        float* dp = out_pos  + (size_t)g0 * 75;
        float* dg = out_gpos + (size_t)g0 * 75;
        float* dr = out_rot  + (size_t)g0 * 225;
        for (int idx = t; idx < NT * 3; idx += THREADS) { dp[idx] = s_pos[idx]; dg[idx] = s_gps[idx]; }
        for (int idx = t; idx < NT * 9; idx += THREADS) dr[idx] = s_rot[idx];
    }
}

extern "C" void kernel_launch(void* const* d_in, const int* in_sizes, int n_in,
                              void* d_out, int out_size)
{
    const float* x = (const float*)d_in[0];
    const int gn = in_sizes[0];          // G * 25
    const int G  = gn / NN;

    const float* off = nullptr;
    const float* axis = nullptr;
    for (int i = 1; i < n_in; i++) {
        if (in_sizes[i] == 6 * gn) off = (const float*)d_in[i];
        else if (in_sizes[i] == 3 * gn && axis == nullptr) axis = (const float*)d_in[i];
    }

    float* out = (float*)d_out;
    float* out_pos  = out;                    // G*N*3
    float* out_rot  = out + (size_t)gn * 3;   // G*N*9
    float* out_gpos = out + (size_t)gn * 12;  // G*N*3
    (void)out_size;

    const int blocks = (G + GPBK - 1) / GPBK;
    fk_kernel<<<blocks, THREADS>>>(x, off, axis, out_pos, out_rot, out_gpos, G);
}

// round 14
// speedup vs baseline: 1.2974x; 1.1407x over previous
#include <cuda_runtime.h>
#include <cstdint>

#define NN     25
#define GPBK   16              // graphs per block
#define THREADS 448
#define LW     12              // fused row: [R0..8 | x,y,z]; 48B, 16B-aligned
#define GROW   (NN * LW)       // 300 floats per graph in s_L

struct A9 { float R[9]; float p[3]; };

__device__ __forceinline__ uint32_t smem_u32(const void* p) {
    return (uint32_t)__cvta_generic_to_shared(p);
}

__device__ __forceinline__ A9 load_row(const float* __restrict__ row) {
    const float4* rp = (const float4*)row;
    const float4 a = rp[0], b = rp[1], c = rp[2];
    A9 o;
    o.R[0]=a.x; o.R[1]=a.y; o.R[2]=a.z; o.R[3]=a.w; o.R[4]=b.x; o.R[5]=b.y;
    o.R[6]=b.z; o.R[7]=b.w; o.R[8]=c.x; o.p[0]=c.y; o.p[1]=c.z; o.p[2]=c.w;
    return o;
}

// W = W ∘ (L, xyz):  p += R*xyz ; R = R*L
__device__ __forceinline__ void step(A9& W, const float* __restrict__ Lrow) {
    const float4* lp = (const float4*)Lrow;
    const float4 LA = lp[0], LB = lp[1], LC = lp[2];
    W.p[0] += W.R[0]*LC.y + W.R[1]*LC.z + W.R[2]*LC.w;
    W.p[1] += W.R[3]*LC.y + W.R[4]*LC.z + W.R[5]*LC.w;
    W.p[2] += W.R[6]*LC.y + W.R[7]*LC.z + W.R[8]*LC.w;
    const float n0 = W.R[0]*LA.x + W.R[1]*LA.w + W.R[2]*LB.z;
    const float n1 = W.R[0]*LA.y + W.R[1]*LB.x + W.R[2]*LB.w;
    const float n2 = W.R[0]*LA.z + W.R[1]*LB.y + W.R[2]*LC.x;
    const float n3 = W.R[3]*LA.x + W.R[4]*LA.w + W.R[5]*LB.z;
    const float n4 = W.R[3]*LA.y + W.R[4]*LB.x + W.R[5]*LB.w;
    const float n5 = W.R[3]*LA.z + W.R[4]*LB.y + W.R[5]*LC.x;
    const float n6 = W.R[6]*LA.x + W.R[7]*LA.w + W.R[8]*LB.z;
    const float n7 = W.R[6]*LA.y + W.R[7]*LB.x + W.R[8]*LB.w;
    const float n8 = W.R[6]*LA.z + W.R[7]*LB.y + W.R[8]*LC.x;
    W.R[0]=n0; W.R[1]=n1; W.R[2]=n2; W.R[3]=n3; W.R[4]=n4;
    W.R[5]=n5; W.R[6]=n6; W.R[7]=n7; W.R[8]=n8;
}

__device__ __forceinline__ void store_w(float* __restrict__ row, const A9& W) {
    float4* rp = (float4*)row;
    rp[0] = make_float4(W.R[0], W.R[1], W.R[2], W.R[3]);
    rp[1] = make_float4(W.R[4], W.R[5], W.R[6], W.R[7]);
    rp[2] = make_float4(W.R[8], W.p[0], W.p[1], W.p[2]);
}

__device__ __forceinline__ void stage_out(int r, const A9& W,
    float rx, float ry, float rz,
    float* __restrict__ s_pos, float* __restrict__ s_gps, float* __restrict__ s_rot)
{
    float* sp = s_pos + r*3;
    float* sg = s_gps + r*3;
    float* sr = s_rot + r*9;
    sp[0]=W.p[0]; sp[1]=W.p[1]; sp[2]=W.p[2];
    sg[0]=W.p[0]+rx; sg[1]=W.p[1]+ry; sg[2]=W.p[2]+rz;
    #pragma unroll
    for (int k=0;k<9;k++) sr[k]=W.R[k];
}

__device__ __forceinline__ void mbar_wait0(uint32_t mb) {
    uint32_t done;
    asm volatile(
        "{\n\t.reg .pred p;\n\t"
        "mbarrier.try_wait.parity.acquire.cta.shared::cta.b64 p, [%1], %2, 0x989680;\n\t"
        "selp.b32 %0, 1, 0, p;\n\t}"
        : "=r"(done) : "r"(mb), "r"(0) : "memory");
    while (!done) {
        asm volatile(
            "{\n\t.reg .pred p;\n\t"
            "mbarrier.try_wait.parity.acquire.cta.shared::cta.b64 p, [%1], %2, 0x989680;\n\t"
            "selp.b32 %0, 1, 0, p;\n\t}"
            : "=r"(done) : "r"(mb), "r"(0) : "memory");
    }
}

__global__ void __launch_bounds__(THREADS, 4)
fk_kernel(const float* __restrict__ x,
          const float* __restrict__ off,
          const float* __restrict__ axis,
          float* __restrict__ out_pos,
          float* __restrict__ out_rot,
          float* __restrict__ out_gpos,
          int G)
{
    __shared__ __align__(16) float s_off[GPBK * NN * 6];   // 9600B; reused as s_W in phase 2
    __shared__ __align__(16) float s_x  [GPBK * NN];       // 1600B
    __shared__ __align__(16) float s_L  [GPBK * GROW];     // 19200B
    __shared__ __align__(16) float s_pos[GPBK * NN * 3];   // 4800B (output layout)
    __shared__ __align__(16) float s_gps[GPBK * NN * 3];   // 4800B
    __shared__ __align__(16) float s_rot[GPBK * NN * 9];   // 14400B
    __shared__ float4 s_ax[NN];
    __shared__ __align__(8) unsigned long long s_mb;
    float* s_W = s_off;   // W rows for nodes 1..6: (g*6 + node-1)*LW

    const int t  = threadIdx.x;
    const int g0 = blockIdx.x * GPBK;
    const int ng = min(GPBK, G - g0);
    const int NT = ng * NN;
    const bool full = (ng == GPBK);

    if (t == 0) {
        const uint32_t mb = smem_u32(&s_mb);
        asm volatile("mbarrier.init.shared.b64 [%0], %1;" :: "r"(mb), "r"(1) : "memory");
    }
    if (t < NN) {
        const float a0 = axis[t*3+0], a1 = axis[t*3+1], a2 = axis[t*3+2];
        s_ax[t] = make_float4(a0, a1, a2, sqrtf(a0*a0 + a1*a1 + a2*a2));
    }
    __syncthreads();

    // ---- stage inputs: TMA bulk (full blocks) or scalar fallback ----
    if (full) {
        if (t == 0) {
            const uint32_t mb = smem_u32(&s_mb);
            asm volatile("mbarrier.arrive.expect_tx.shared.b64 _, [%0], %1;"
                         :: "r"(mb), "r"(GPBK * 600 + GPBK * 100) : "memory");
            asm volatile("cp.async.bulk.shared::cluster.global.mbarrier::complete_tx::bytes "
                         "[%0], [%1], %2, [%3];"
                         :: "r"(smem_u32(s_off)), "l"(off + (size_t)g0 * 150),
                            "r"(GPBK * 600), "r"(mb) : "memory");
            asm volatile("cp.async.bulk.shared::cluster.global.mbarrier::complete_tx::bytes "
                         "[%0], [%1], %2, [%3];"
                         :: "r"(smem_u32(s_x)), "l"(x + (size_t)g0 * NN),
                            "r"(GPBK * 100), "r"(mb) : "memory");
        }
        mbar_wait0(smem_u32(&s_mb));
    } else {
        const float* src = off + (size_t)g0 * 150;
        for (int i = t; i < NT * 6; i += THREADS) s_off[i] = src[i];
        for (int i = t; i < NT; i += THREADS) s_x[i] = x[(size_t)g0 * NN + i];
        __syncthreads();
    }

    // ---- phase 1: per-node local matrix -> fused row [L0..8, ox,oy,oz] ----
    if (t < NT) {
        const int i = t - 25 * (t / 25);
        const float2* o2 = (const float2*)(s_off + t * 6);   // 24B-aligned
        const float2 oA = o2[0], oB = o2[1], oC = o2[2];
        const float4 ax = s_ax[i];
        const float th = s_x[t] * ax.w;
        const float ox = oA.x, oy = oA.y, oz = oB.x;

        float sx,cx,sy,cy,sz,cz,st,ct;
        __sincosf(oB.y, &sx, &cx);
        __sincosf(oC.x, &sy, &cy);
        __sincosf(oC.y, &sz, &cz);
        __sincosf(th,  &st, &ct);

        const float e00=cz*cy,            e10=sz*cy,            e20=-sy;
        const float e01=cz*sy*sx - sz*cx, e11=sz*sy*sx + cz*cx, e21=cy*sx;
        const float e02=cz*sy*cx + sz*sx, e12=sz*sy*cx - cz*sx, e22=cy*cx;

        const float v=1.f-ct, n1=ax.x, n2=ax.y, n3=ax.z;
        const float n12v=n1*n2*v, n13v=n1*n3*v, n23v=n2*n3*v;
        const float r00=ct+n1*n1*v, r01=n12v-n3*st, r02=n13v+n2*st;
        const float r10=n12v+n3*st, r11=ct+n2*n2*v, r12=n23v-n1*st;
        const float r20=n13v-n2*st, r21=n23v+n1*st, r22=ct+n3*n3*v;

        float4 A, B, C;
        A.x=e00*r00+e01*r10+e02*r20; A.y=e00*r01+e01*r11+e02*r21; A.z=e00*r02+e01*r12+e02*r22;
        A.w=e10*r00+e11*r10+e12*r20; B.x=e10*r01+e11*r11+e12*r21; B.y=e10*r02+e11*r12+e12*r22;
        B.z=e20*r00+e21*r10+e22*r20; B.w=e20*r01+e21*r11+e22*r21; C.x=e20*r02+e21*r12+e22*r22;
        C.y=ox; C.z=oy; C.w=oz;

        float4* row = (float4*)(s_L + t * LW);
        row[0] = A; row[1] = B; row[2] = C;
    }
    __syncthreads();   // s_off no longer read; safe to write s_W below

    // ---- phase 2a level 1: nodes 1,2 (1 warp, packed across graphs) ----
    if (t < 2 * GPBK) {
        const int g = t >> 1, node = 1 + (t & 1);
        if (g < ng) {
            const float* Lg = s_L + g * GROW;
            A9 W = load_row(Lg);                      // (L0 | xyz0)
            const float rx = W.p[0], ry = W.p[1], rz = W.p[2];
            W.p[0] = 0.f; W.p[1] = 0.f; W.p[2] = 0.f; // W0 = (L0, 0)
            step(W, Lg + node * LW);
            store_w(s_W + (g*6 + node-1) * LW, W);
            stage_out(g*NN + node, W, rx, ry, rz, s_pos, s_gps, s_rot);
        }
    }
    __syncthreads();

    // ---- phase 2a level 2: nodes 3..6 (2 warps) ----
    if (t < 4 * GPBK) {
        const int g = t >> 2, j = t & 3, node = 3 + j, par = 1 + (j >> 1);
        if (g < ng) {
            const float* Lg = s_L + g * GROW;
            A9 W = load_row(s_W + (g*6 + par-1) * LW);
            step(W, Lg + node * LW);
            store_w(s_W + (g*6 + node-1) * LW, W);
            stage_out(g*NN + node, W, Lg[9], Lg[10], Lg[11], s_pos, s_gps, s_rot);
        }
    }
    __syncthreads();

    // ---- phase 2b: short walks from level-2 ancestors + root staging ----
    if (t < 160) {                       // depth-4 leaves 15..24: 2 steps (5 warps)
        const int g = t / 10, j = t - g * 10, node = 15 + j;
        const int anc3 = 7 + (j >> 1), anc2 = 3 + (j >> 2);
        if (g < ng) {
            const float* Lg = s_L + g * GROW;
            A9 W = load_row(s_W + (g*6 + anc2-1) * LW);
            step(W, Lg + anc3 * LW);
            step(W, Lg + node * LW);
            stage_out(g*NN + node, W, Lg[9], Lg[10], Lg[11], s_pos, s_gps, s_rot);
        }
    } else if (t < 288) {                // depth-3 nodes 7..14: 1 step (4 warps)
        const int i = t - 160, g = i >> 3, j = i & 7, node = 7 + j, par = 3 + (j >> 1);
        if (g < ng) {
            const float* Lg = s_L + g * GROW;
            A9 W = load_row(s_W + (g*6 + par-1) * LW);
            step(W, Lg + node * LW);
            stage_out(g*NN + node, W, Lg[9], Lg[10], Lg[11], s_pos, s_gps, s_rot);
        }
    } else if (t < 288 + GPBK) {         // root outputs (half warp)
        const int g = t - 288;
        if (g < ng) {
            const float* Lg = s_L + g * GROW;
            A9 W = load_row(Lg);
            const float rx = W.p[0], ry = W.p[1], rz = W.p[2];
            W.p[0] = 0.f; W.p[1] = 0.f; W.p[2] = 0.f;
            stage_out(g*NN, W, rx, ry, rz, s_pos, s_gps, s_rot);
        }
    }
    __syncthreads();

    // ---- flush: TMA bulk stores (full blocks) or scalar fallback ----
    if (full) {
        if (t == 0) {
            asm volatile("fence.proxy.async.shared::cta;" ::: "memory");
            asm volatile("cp.async.bulk.global.shared::cta.bulk_group [%0], [%1], %2;"
                         :: "l"(out_pos + (size_t)g0 * 75), "r"(smem_u32(s_pos)),
                            "r"(GPBK * 300) : "memory");
            asm volatile("cp.async.bulk.global.shared::cta.bulk_group [%0], [%1], %2;"
                         :: "l"(out_gpos + (size_t)g0 * 75), "r"(smem_u32(s_gps)),
                            "r"(GPBK * 300) : "memory");
            asm volatile("cp.async.bulk.global.shared::cta.bulk_group [%0], [%1], %2;"
                         :: "l"(out_rot + (size_t)g0 * 225), "r"(smem_u32(s_rot)),
                            "r"(GPBK * 900) : "memory");
            asm volatile("cp.async.bulk.commit_group;" ::: "memory");
            asm volatile("cp.async.bulk.wait_group 0;" ::: "memory");
        }
    } else {
        float* dp = out_pos  + (size_t)g0 * 75;
        float* dg = out_gpos + (size_t)g0 * 75;
        float* dr = out_rot  + (size_t)g0 * 225;
        for (int idx = t; idx < NT * 3; idx += THREADS) { dp[idx] = s_pos[idx]; dg[idx] = s_gps[idx]; }
        for (int idx = t; idx < NT * 9; idx += THREADS) dr[idx] = s_rot[idx];
    }
}

extern "C" void kernel_launch(void* const* d_in, const int* in_sizes, int n_in,
                              void* d_out, int out_size)
{
    const float* x = (const float*)d_in[0];
    const int gn = in_sizes[0];          // G * 25
    const int G  = gn / NN;

    const float* off = nullptr;
    const float* axis = nullptr;
    for (int i = 1; i < n_in; i++) {
        if (in_sizes[i] == 6 * gn) off = (const float*)d_in[i];
        else if (in_sizes[i] == 3 * gn && axis == nullptr) axis = (const float*)d_in[i];
    }

    float* out = (float*)d_out;
    float* out_pos  = out;                    // G*N*3
    float* out_rot  = out + (size_t)gn * 3;   // G*N*9
    float* out_gpos = out + (size_t)gn * 12;  // G*N*3
    (void)out_size;

    const int blocks = (G + GPBK - 1) / GPBK;
    fk_kernel<<<blocks, THREADS>>>(x, off, axis, out_pos, out_rot, out_gpos, G);
}